// round 1
// baseline (speedup 1.0000x reference)
#include <cuda_runtime.h>

// Problem dims
#define NB 8
#define NS 4096
#define NF 256
#define NI 512
#define NI3 1536
#define ND 4
#define NKT 7
#define NV 256

// ---------------- device scratch (no allocations allowed) ----------------
__device__ float g_P[(size_t)NB * NF * NS];            // x-buffer A (33.5 MB)
__device__ float g_Q[(size_t)NB * NF * NS];            // x-buffer B (33.5 MB)
__device__ float g_y[(size_t)NB * NI3 * NS];           // 3I-wide activations (201 MB)
__device__ float g_v[(size_t)NB * NI * NS];            // lin_attn output (67 MB)
__device__ float g_w1t[(size_t)ND * NKT * NI3 * NI];   // transposed conv weights (88 MB)

typedef unsigned long long u64;

// ---------------- packed f32x2 helpers (sm_100+/sm_103a) ----------------
__device__ __forceinline__ u64 ffma2(u64 a, u64 b, u64 c) {
    u64 d;
    asm("fma.rn.f32x2 %0, %1, %2, %3;" : "=l"(d) : "l"(a), "l"(b), "l"(c));
    return d;
}
__device__ __forceinline__ u64 pk2(float x) {
    u64 d;
    asm("mov.b64 %0, {%1, %1};" : "=l"(d) : "f"(x));
    return d;
}
__device__ __forceinline__ float2 upk(u64 d) {
    float2 r;
    asm("mov.b64 {%0, %1}, %2;" : "=f"(r.x), "=f"(r.y) : "l"(d));
    return r;
}

// mish(x) = x * tanh(softplus(x)) = x * (t^2+2t)/(t^2+2t+2), t=e^x
__device__ __forceinline__ float mishf(float x) {
    if (x > 20.0f) return x;                 // also avoids e^x overflow -> NaN
    float t = __expf(x);
    float u = t * t + 2.0f * t;
    return x * (u / (u + 2.0f));
}

// ---------------- shared 128x128x8 micro-kernel ----------------
// acc[p][j]: rows (warp*16 + 2p, +1) packed in f32x2 lanes, col lane*4 + j.
__device__ __forceinline__ void mm8(const float (*As)[128], const float (*Bs)[128],
                                    u64 acc[8][4], int lane, int warp) {
#pragma unroll
    for (int kk = 0; kk < 8; kk++) {
        u64 a[8];
#pragma unroll
        for (int q = 0; q < 4; q++) {
            ulonglong2 t2 = *(const ulonglong2*)&As[kk][warp * 16 + q * 4];
            a[2 * q] = t2.x;
            a[2 * q + 1] = t2.y;
        }
        float4 bv = *(const float4*)&Bs[kk][lane * 4];
        u64 b0 = pk2(bv.x), b1 = pk2(bv.y), b2 = pk2(bv.z), b3 = pk2(bv.w);
#pragma unroll
        for (int p = 0; p < 8; p++) {
            acc[p][0] = ffma2(a[p], b0, acc[p][0]);
            acc[p][1] = ffma2(a[p], b1, acc[p][1]);
            acc[p][2] = ffma2(a[p], b2, acc[p][2]);
            acc[p][3] = ffma2(a[p], b3, acc[p][3]);
        }
    }
}

// ---------------- embedding gather ----------------
__global__ void embed_kernel(const int* __restrict__ inp, const float* __restrict__ emb) {
    int sx = threadIdx.x & 63, cg = threadIdx.x >> 6;
    int s = blockIdx.x * 64 + sx;
    int b = blockIdx.y;
    int idx = inp[b * NS + s];
    const float* er = emb + (size_t)idx * (2 * NF);
#pragma unroll 4
    for (int c = cg; c < NF; c += 4) {
        g_P[((size_t)b * NF + c) * NS + s] = er[c];
        g_Q[((size_t)b * NF + c) * NS + s] = er[c + NF];
    }
}

// ---------------- w1 transpose: [d][o][i][k] -> [d][k][o][i] ----------------
__global__ void w1t_kernel(const float* __restrict__ w1) {
    size_t idx = (size_t)blockIdx.x * 256 + threadIdx.x;
    int i = (int)(idx & (NI - 1));
    size_t r = idx / NI;
    int o = (int)(r % NI3);
    r /= NI3;
    int t = (int)(r % NKT);
    int d = (int)(r / NKT);
    g_w1t[idx] = w1[(((size_t)d * NI3 + o) * NI + i) * NKT + t];
}

// ---------------- lin_attn: cumsum(depth)/t * scale + shift ----------------
__global__ void linattn_kernel() {
    int i = blockIdx.x, b = blockIdx.y, t = threadIdx.x;
    const float* dr = g_y + ((size_t)b * NI3 + i) * NS + t * 16;
    const float* sc = g_y + ((size_t)b * NI3 + NI + i) * NS + t * 16;
    const float* sh = g_y + ((size_t)b * NI3 + 2 * NI + i) * NS + t * 16;
    float* op = g_v + ((size_t)b * NI + i) * NS + t * 16;

    float loc[16];
#pragma unroll
    for (int q = 0; q < 4; q++) {
        float4 f = ((const float4*)dr)[q];
        loc[q * 4 + 0] = f.x;
        loc[q * 4 + 1] = f.y;
        loc[q * 4 + 2] = f.z;
        loc[q * 4 + 3] = f.w;
    }
#pragma unroll
    for (int j = 1; j < 16; j++) loc[j] += loc[j - 1];
    float tot = loc[15];

    // warp-inclusive scan of per-thread totals
    float v = tot;
#pragma unroll
    for (int o = 1; o < 32; o <<= 1) {
        float n = __shfl_up_sync(0xffffffffu, v, o);
        if ((t & 31) >= o) v += n;
    }
    __shared__ float wsum[8];
    if ((t & 31) == 31) wsum[t >> 5] = v;
    __syncthreads();
    if (t == 0) {
        float run = 0.0f;
#pragma unroll
        for (int k = 0; k < 8; k++) {
            float w = wsum[k];
            wsum[k] = run;
            run += w;
        }
    }
    __syncthreads();
    float excl = wsum[t >> 5] + (v - tot);

    int sbase = t * 16;
#pragma unroll
    for (int q = 0; q < 4; q++) {
        float4 scv = ((const float4*)sc)[q];
        float4 shv = ((const float4*)sh)[q];
        float4 o4;
        o4.x = (excl + loc[q * 4 + 0]) / (float)(sbase + q * 4 + 1) * scv.x + shv.x;
        o4.y = (excl + loc[q * 4 + 1]) / (float)(sbase + q * 4 + 2) * scv.y + shv.y;
        o4.z = (excl + loc[q * 4 + 2]) / (float)(sbase + q * 4 + 3) * scv.z + shv.z;
        o4.w = (excl + loc[q * 4 + 3]) / (float)(sbase + q * 4 + 4) * scv.w + shv.w;
        ((float4*)op)[q] = o4;
    }
}

// ---------------- generic SGEMM over [M x K] * [K x S] per batch ----------------
// bsrc: 0=g_P, 1=g_Q, 2=g_v, 3=concat(P rows 0..255, Q rows 256..511)
// cmode: 0 -> g_y = mish(acc); 1 -> g_P += acc; 2 -> g_Q += acc; 3 -> Cext = acc + bias[row]
__global__ void __launch_bounds__(256, 2) sgemm_kernel(
    const float* __restrict__ A, int lda, int Kdim,
    int bsrc, int cmode, float* __restrict__ Cext, const float* __restrict__ bias)
{
    __shared__ __align__(16) float As[8][128];
    __shared__ __align__(16) float Bs[8][128];
    int t = threadIdx.x, lane = t & 31, warp = t >> 5;
    int n0 = blockIdx.x * 128, m0 = blockIdx.y * 128, b = blockIdx.z;

    u64 acc[8][4];
#pragma unroll
    for (int p = 0; p < 8; p++)
#pragma unroll
        for (int j = 0; j < 4; j++) acc[p][j] = 0ull;

    int arow = t >> 1;
    int acol0 = (t & 1) * 4;
    int bkk = t >> 5;
    int bn = (t & 31) * 4;
    const float* Aptr = A + (size_t)(m0 + arow) * lda + acol0;

    auto ldB = [&](int k0) -> float4 {
        int kr = k0 + bkk;
        const float* Bp;
        if (bsrc == 0)      Bp = g_P + ((size_t)b * NF + kr) * NS;
        else if (bsrc == 1) Bp = g_Q + ((size_t)b * NF + kr) * NS;
        else if (bsrc == 2) Bp = g_v + ((size_t)b * NI + kr) * NS;
        else Bp = (kr < NF) ? g_P + ((size_t)b * NF + kr) * NS
                            : g_Q + ((size_t)b * NF + (kr - NF)) * NS;
        return *(const float4*)(Bp + n0 + bn);
    };

    float4 aR = *(const float4*)(Aptr);
    float4 bR = ldB(0);
    int KT = Kdim >> 3;
    for (int kt = 0; kt < KT; kt++) {
        As[acol0 + 0][arow] = aR.x;
        As[acol0 + 1][arow] = aR.y;
        As[acol0 + 2][arow] = aR.z;
        As[acol0 + 3][arow] = aR.w;
        *(float4*)&Bs[bkk][bn] = bR;
        __syncthreads();
        if (kt + 1 < KT) {
            aR = *(const float4*)(Aptr + (kt + 1) * 8);
            bR = ldB((kt + 1) * 8);
        }
        mm8(As, Bs, acc, lane, warp);
        __syncthreads();
    }

    int r0 = m0 + warp * 16;
    int c0 = n0 + lane * 4;
#pragma unroll
    for (int p = 0; p < 8; p++) {
        float2 u0 = upk(acc[p][0]);
        float2 u1 = upk(acc[p][1]);
        float2 u2 = upk(acc[p][2]);
        float2 u3 = upk(acc[p][3]);
        int rA = r0 + 2 * p;
        if (cmode == 0) {
            float4 vA = make_float4(mishf(u0.x), mishf(u1.x), mishf(u2.x), mishf(u3.x));
            float4 vB = make_float4(mishf(u0.y), mishf(u1.y), mishf(u2.y), mishf(u3.y));
            *(float4*)(g_y + ((size_t)b * NI3 + rA) * NS + c0) = vA;
            *(float4*)(g_y + ((size_t)b * NI3 + rA + 1) * NS + c0) = vB;
        } else if (cmode == 1 || cmode == 2) {
            float* X = (cmode == 1) ? g_P : g_Q;
            float4* p0 = (float4*)(X + ((size_t)b * NF + rA) * NS + c0);
            float4* p1 = (float4*)(X + ((size_t)b * NF + rA + 1) * NS + c0);
            float4 e0 = *p0, e1 = *p1;
            e0.x += u0.x; e0.y += u1.x; e0.z += u2.x; e0.w += u3.x;
            e1.x += u0.y; e1.y += u1.y; e1.z += u2.y; e1.w += u3.y;
            *p0 = e0;
            *p1 = e1;
        } else {
            float bbA = bias[rA], bbB = bias[rA + 1];
            float4 vA = make_float4(u0.x + bbA, u1.x + bbA, u2.x + bbA, u3.x + bbA);
            float4 vB = make_float4(u0.y + bbB, u1.y + bbB, u2.y + bbB, u3.y + bbB);
            *(float4*)(Cext + ((size_t)b * NV + rA) * NS + c0) = vA;
            *(float4*)(Cext + ((size_t)b * NV + rA + 1) * NS + c0) = vB;
        }
    }
}

// ---------------- causal conv as 7-tap implicit GEMM: g_y = mish(w1 (*) g_v) ----------------
__global__ void __launch_bounds__(256, 2) conv_gemm_kernel(int d) {
    __shared__ __align__(16) float As[8][128];
    __shared__ __align__(16) float Bs[8][128];
    int t = threadIdx.x, lane = t & 31, warp = t >> 5;
    int n0 = blockIdx.x * 128, m0 = blockIdx.y * 128, b = blockIdx.z;

    u64 acc[8][4];
#pragma unroll
    for (int p = 0; p < 8; p++)
#pragma unroll
        for (int j = 0; j < 4; j++) acc[p][j] = 0ull;

    int arow = t >> 1;
    int acol0 = (t & 1) * 4;
    int bkk = t >> 5;
    int bn = (t & 31) * 4;

    auto ldA = [&](int kt) -> float4 {
        int tap = kt >> 6, ic = kt & 63;
        return *(const float4*)(g_w1t +
            (((size_t)(d * NKT + tap) * NI3 + m0 + arow) * NI + ic * 8 + acol0));
    };
    auto ldB = [&](int kt) -> float4 {
        int tap = kt >> 6, ic = kt & 63;
        int i = ic * 8 + bkk;
        const float* vr = g_v + ((size_t)b * NI + i) * NS;
        int sb = n0 + bn + tap - (NKT - 1);
        float4 r;
        r.x = (sb + 0 >= 0) ? vr[sb + 0] : 0.0f;
        r.y = (sb + 1 >= 0) ? vr[sb + 1] : 0.0f;
        r.z = (sb + 2 >= 0) ? vr[sb + 2] : 0.0f;
        r.w = (sb + 3 >= 0) ? vr[sb + 3] : 0.0f;
        return r;
    };

    const int KT = NKT * 64;  // 7 taps x (512/8) chunks
    float4 aR = ldA(0);
    float4 bR = ldB(0);
    for (int kt = 0; kt < KT; kt++) {
        As[acol0 + 0][arow] = aR.x;
        As[acol0 + 1][arow] = aR.y;
        As[acol0 + 2][arow] = aR.z;
        As[acol0 + 3][arow] = aR.w;
        *(float4*)&Bs[bkk][bn] = bR;
        __syncthreads();
        if (kt + 1 < KT) {
            aR = ldA(kt + 1);
            bR = ldB(kt + 1);
        }
        mm8(As, Bs, acc, lane, warp);
        __syncthreads();
    }

    int r0 = m0 + warp * 16;
    int c0 = n0 + lane * 4;
#pragma unroll
    for (int p = 0; p < 8; p++) {
        float2 u0 = upk(acc[p][0]);
        float2 u1 = upk(acc[p][1]);
        float2 u2 = upk(acc[p][2]);
        float2 u3 = upk(acc[p][3]);
        int rA = r0 + 2 * p;
        float4 vA = make_float4(mishf(u0.x), mishf(u1.x), mishf(u2.x), mishf(u3.x));
        float4 vB = make_float4(mishf(u0.y), mishf(u1.y), mishf(u2.y), mishf(u3.y));
        *(float4*)(g_y + ((size_t)b * NI3 + rA) * NS + c0) = vA;
        *(float4*)(g_y + ((size_t)b * NI3 + rA + 1) * NS + c0) = vB;
    }
}

// ---------------- launch ----------------
extern "C" void kernel_launch(void* const* d_in, const int* in_sizes, int n_in,
                              void* d_out, int out_size) {
    (void)in_sizes; (void)n_in; (void)out_size;
    const int* inp = (const int*)d_in[0];
    const float* emb = (const float*)d_in[1];
    const float* w0 = (const float*)d_in[2];
    const float* w1 = (const float*)d_in[3];
    const float* w2 = (const float*)d_in[4];
    const float* out_w = (const float*)d_in[5];
    const float* out_b = (const float*)d_in[6];
    float* out = (float*)d_out;

    embed_kernel<<<dim3(NS / 64, NB), 256>>>(inp, emb);
    w1t_kernel<<<(int)(((size_t)ND * NKT * NI3 * NI) / 256), 256>>>(w1);

    // Reversible stack, statically unrolled buffer roles:
    // even d: x1 = Q (input), accumulate cell into P; odd d: reversed.
    for (int d = 0; d < ND; d++) {
        int insel = (d % 2 == 0) ? 1 : 0;   // bsrc for cell input
        int accm  = (d % 2 == 0) ? 1 : 2;   // cmode: accumulate destination
        sgemm_kernel<<<dim3(NS / 128, NI3 / 128, NB), 256>>>(
            w0 + (size_t)d * NI3 * NF, NF, NF, insel, 0, nullptr, nullptr);
        linattn_kernel<<<dim3(NI, NB), 256>>>();
        conv_gemm_kernel<<<dim3(NS / 128, NI3 / 128, NB), 256>>>(d);
        linattn_kernel<<<dim3(NI, NB), 256>>>();
        sgemm_kernel<<<dim3(NS / 128, NF / 128, NB), 256>>>(
            w2 + (size_t)d * NF * NI, NI, NI, 2, accm, nullptr, nullptr);
    }

    // final: out = out_w[:, :256] @ P + out_w[:, 256:] @ Q + bias
    sgemm_kernel<<<dim3(NS / 128, NV / 128, NB), 256>>>(
        out_w, 2 * NF, 2 * NF, 3, 3, out, out_b);
}

// round 3
// speedup vs baseline: 2.0115x; 2.0115x over previous
#include <cuda_runtime.h>
#include <cstdint>

// Problem dims
#define NB 8
#define NS 4096
#define NF 256
#define NI 512
#define NI3 1536
#define ND 4
#define NKT 7
#define NV 256

#define SROW 20   // smem row stride (floats) for [row][k16] tiles; conflict-free

// ---------------- device scratch (no allocations allowed) ----------------
__device__ float g_P[(size_t)NB * NF * NS];            // [b][c][s]
__device__ float g_Q[(size_t)NB * NF * NS];            // [b][c][s]
__device__ float g_y[(size_t)NB * NI3 * NS];           // [b][c][s]
__device__ float g_v[(size_t)NB * NI * NS];            // [b][i][s]
__device__ float g_xt[(size_t)NB * NS * NF];           // [b][s][256]
__device__ float g_vt[(size_t)NB * NS * NI];           // [b][s][512]
__device__ float g_w1t[(size_t)ND * NKT * NI3 * NI];   // [d][tap][o][i]

// ---------------- helpers ----------------
__device__ __forceinline__ uint32_t tf32c(float f) {
    uint32_t r;
    asm("cvt.rna.tf32.f32 %0, %1;" : "=r"(r) : "f"(f));
    return r;
}
__device__ __forceinline__ void mma_tf32(float c[4], uint32_t a0, uint32_t a1,
                                         uint32_t a2, uint32_t a3,
                                         uint32_t b0, uint32_t b1) {
    asm("mma.sync.aligned.m16n8k8.row.col.f32.tf32.tf32.f32 "
        "{%0,%1,%2,%3}, {%4,%5,%6,%7}, {%8,%9}, {%0,%1,%2,%3};"
        : "+f"(c[0]), "+f"(c[1]), "+f"(c[2]), "+f"(c[3])
        : "r"(a0), "r"(a1), "r"(a2), "r"(a3), "r"(b0), "r"(b1));
}
__device__ __forceinline__ float mishf(float x) {
    if (x > 20.0f) return x;
    float t = __expf(x);
    float u = t * t + 2.0f * t;
    return x * (u / (u + 2.0f));
}

// ---------------- embedding gather ----------------
__global__ void embed_kernel(const int* __restrict__ inp, const float* __restrict__ emb) {
    int sx = threadIdx.x & 63, cg = threadIdx.x >> 6;
    int s = blockIdx.x * 64 + sx;
    int b = blockIdx.y;
    int idx = inp[b * NS + s];
    const float* er = emb + (size_t)idx * (2 * NF);
#pragma unroll 4
    for (int c = cg; c < NF; c += 4) {
        g_P[((size_t)b * NF + c) * NS + s] = er[c];
        g_Q[((size_t)b * NF + c) * NS + s] = er[c + NF];
    }
}

// ---------------- w1 transpose: [d][o][i][k] -> [d][k][o][i] ----------------
__global__ void w1t_kernel(const float* __restrict__ w1) {
    size_t idx = (size_t)blockIdx.x * 256 + threadIdx.x;
    int i = (int)(idx & (NI - 1));
    size_t r = idx / NI;
    int o = (int)(r % NI3);
    r /= NI3;
    int t = (int)(r % NKT);
    int d = (int)(r / NKT);
    g_w1t[idx] = w1[(((size_t)d * NI3 + o) * NI + i) * NKT + t];
}

// ---------------- activation transpose [b][C][S] -> dst[b][s][dstride]+doff ----------------
__global__ void transpose_kernel(const float* __restrict__ src, float* __restrict__ dst,
                                 int C, int dstride, int doff) {
    __shared__ float tl[32][33];
    int b = blockIdx.z, c0 = blockIdx.y * 32, s0 = blockIdx.x * 32;
    int tx = threadIdx.x, ty = threadIdx.y;
#pragma unroll
    for (int q = 0; q < 4; q++) {
        int c = ty + q * 8;
        tl[c][tx] = src[((size_t)b * C + c0 + c) * NS + s0 + tx];
    }
    __syncthreads();
#pragma unroll
    for (int q = 0; q < 4; q++) {
        int s = ty + q * 8;
        dst[((size_t)b * NS + s0 + s) * dstride + doff + c0 + tx] = tl[tx][s];
    }
}

// ---------------- lin_attn ----------------
__global__ void linattn_kernel() {
    int i = blockIdx.x, b = blockIdx.y, t = threadIdx.x;
    const float* dr = g_y + ((size_t)b * NI3 + i) * NS + t * 16;
    const float* sc = g_y + ((size_t)b * NI3 + NI + i) * NS + t * 16;
    const float* sh = g_y + ((size_t)b * NI3 + 2 * NI + i) * NS + t * 16;
    float* op = g_v + ((size_t)b * NI + i) * NS + t * 16;

    float loc[16];
#pragma unroll
    for (int q = 0; q < 4; q++) {
        float4 f = ((const float4*)dr)[q];
        loc[q * 4 + 0] = f.x; loc[q * 4 + 1] = f.y;
        loc[q * 4 + 2] = f.z; loc[q * 4 + 3] = f.w;
    }
#pragma unroll
    for (int j = 1; j < 16; j++) loc[j] += loc[j - 1];
    float tot = loc[15];

    float v = tot;
#pragma unroll
    for (int o = 1; o < 32; o <<= 1) {
        float n = __shfl_up_sync(0xffffffffu, v, o);
        if ((t & 31) >= o) v += n;
    }
    __shared__ float wsum[8];
    if ((t & 31) == 31) wsum[t >> 5] = v;
    __syncthreads();
    if (t == 0) {
        float run = 0.0f;
#pragma unroll
        for (int k = 0; k < 8; k++) { float w = wsum[k]; wsum[k] = run; run += w; }
    }
    __syncthreads();
    float excl = wsum[t >> 5] + (v - tot);

    int sbase = t * 16;
#pragma unroll
    for (int q = 0; q < 4; q++) {
        float4 scv = ((const float4*)sc)[q];
        float4 shv = ((const float4*)sh)[q];
        float4 o4;
        o4.x = (excl + loc[q * 4 + 0]) / (float)(sbase + q * 4 + 1) * scv.x + shv.x;
        o4.y = (excl + loc[q * 4 + 1]) / (float)(sbase + q * 4 + 2) * scv.y + shv.y;
        o4.z = (excl + loc[q * 4 + 2]) / (float)(sbase + q * 4 + 3) * scv.z + shv.z;
        o4.w = (excl + loc[q * 4 + 3]) / (float)(sbase + q * 4 + 4) * scv.w + shv.w;
        ((float4*)op)[q] = o4;
    }
}

// ---------------- unified tf32 warp-MMA GEMM ----------------
// C[M x Nseq] = A[M x K] * B[K x Nseq] per batch.
// A: row-major weights (conv: g_w1t layout, tap-chunked).
// B: activations [b][s][bstride] (k contiguous per row). conv: tap-shifted, causal 0-fill.
// cmode: 0 -> g_y = mish(acc); 1 -> g_P += acc; 2 -> g_Q += acc; 3 -> Cext = acc + bias.
__global__ void __launch_bounds__(256, 2) mma_gemm(
    const float* __restrict__ A, int lda, int Kdim, int conv,
    const float* __restrict__ B, int bstride,
    int cmode, float* __restrict__ Cext, const float* __restrict__ bias)
{
    __shared__ uint32_t As[128 * SROW];
    __shared__ uint32_t Bs[128 * SROW];
    int t = threadIdx.x, lane = t & 31, warp = t >> 5;
    int n0 = blockIdx.x * 128, m0 = blockIdx.y * 128, b = blockIdx.z;
    int row = t >> 1, kk0 = (t & 1) * 8;
    int wm = (warp >> 2) * 64, wn = (warp & 3) * 32;

    float acc[4][4][4];
#pragma unroll
    for (int mi = 0; mi < 4; mi++)
#pragma unroll
        for (int ni = 0; ni < 4; ni++)
#pragma unroll
            for (int q = 0; q < 4; q++) acc[mi][ni][q] = 0.0f;

    const int KT = conv ? (NKT * NI / 16) : (Kdim >> 4);

    auto ldA = [&](int kt, float4& x, float4& y) {
        const float* p;
        if (conv) {
            int tap = kt >> 5, ic = ((kt & 31) << 4) + kk0;
            p = A + ((size_t)tap * NI3 + m0 + row) * NI + ic;
        } else {
            p = A + (size_t)(m0 + row) * lda + (kt << 4) + kk0;
        }
        x = ((const float4*)p)[0];
        y = ((const float4*)p)[1];
    };
    auto ldB = [&](int kt, float4& x, float4& y) {
        if (conv) {
            int tap = kt >> 5, ic = ((kt & 31) << 4) + kk0;
            int s = n0 + row + tap - (NKT - 1);
            if (s < 0) {
                x = make_float4(0.f, 0.f, 0.f, 0.f);
                y = x;
            } else {
                const float* p = B + ((size_t)b * NS + s) * bstride + ic;
                x = ((const float4*)p)[0];
                y = ((const float4*)p)[1];
            }
        } else {
            const float* p = B + ((size_t)b * NS + n0 + row) * bstride + (kt << 4) + kk0;
            x = ((const float4*)p)[0];
            y = ((const float4*)p)[1];
        }
    };
    auto stS = [&](uint32_t* S, float4 x, float4 y) {
        uint32_t* p = S + row * SROW + kk0;
        p[0] = tf32c(x.x); p[1] = tf32c(x.y); p[2] = tf32c(x.z); p[3] = tf32c(x.w);
        p[4] = tf32c(y.x); p[5] = tf32c(y.y); p[6] = tf32c(y.z); p[7] = tf32c(y.w);
    };

    float4 ax, ay, bx, by;
    ldA(0, ax, ay);
    ldB(0, bx, by);

    for (int kt = 0; kt < KT; kt++) {
        stS(As, ax, ay);
        stS(Bs, bx, by);
        __syncthreads();
        if (kt + 1 < KT) {
            ldA(kt + 1, ax, ay);
            ldB(kt + 1, bx, by);
        }
#pragma unroll
        for (int h = 0; h < 2; h++) {
            int k0 = h * 8 + (lane & 3);
            uint32_t bf[4][2];
#pragma unroll
            for (int ni = 0; ni < 4; ni++) {
                const uint32_t* bp = Bs + (wn + ni * 8 + (lane >> 2)) * SROW + k0;
                bf[ni][0] = bp[0];
                bf[ni][1] = bp[4];
            }
#pragma unroll
            for (int mi = 0; mi < 4; mi++) {
                const uint32_t* ap = As + (wm + mi * 16 + (lane >> 2)) * SROW + k0;
                uint32_t a0 = ap[0], a1 = ap[8 * SROW], a2 = ap[4], a3 = ap[8 * SROW + 4];
#pragma unroll
                for (int ni = 0; ni < 4; ni++)
                    mma_tf32(acc[mi][ni], a0, a1, a2, a3, bf[ni][0], bf[ni][1]);
            }
        }
        __syncthreads();
    }

    // epilogue: thread owns (m, n) pairs: rows r, r+8; cols 2*(lane%4)+{0,1}
#pragma unroll
    for (int mi = 0; mi < 4; mi++) {
        int mlo = m0 + wm + mi * 16 + (lane >> 2);
#pragma unroll
        for (int ni = 0; ni < 4; ni++) {
            int n = n0 + wn + ni * 8 + 2 * (lane & 3);
            float* cc = acc[mi][ni];
#pragma unroll
            for (int hh = 0; hh < 2; hh++) {
                int m = mlo + hh * 8;
                float v0 = cc[hh * 2 + 0], v1 = cc[hh * 2 + 1];
                if (cmode == 0) {
                    float2 o = make_float2(mishf(v0), mishf(v1));
                    *(float2*)(g_y + ((size_t)b * NI3 + m) * NS + n) = o;
                } else if (cmode == 1 || cmode == 2) {
                    float* X = (cmode == 1) ? g_P : g_Q;
                    float2* p = (float2*)(X + ((size_t)b * NF + m) * NS + n);
                    float2 e = *p;
                    e.x += v0; e.y += v1;
                    *p = e;
                } else {
                    float bb = bias[m];
                    float2 o = make_float2(v0 + bb, v1 + bb);
                    *(float2*)(Cext + ((size_t)b * NV + m) * NS + n) = o;
                }
            }
        }
    }
}

// ---------------- launch ----------------
extern "C" void kernel_launch(void* const* d_in, const int* in_sizes, int n_in,
                              void* d_out, int out_size) {
    (void)in_sizes; (void)n_in; (void)out_size;
    const int* inp = (const int*)d_in[0];
    const float* emb = (const float*)d_in[1];
    const float* w0 = (const float*)d_in[2];
    const float* w1 = (const float*)d_in[3];
    const float* w2 = (const float*)d_in[4];
    const float* out_w = (const float*)d_in[5];
    const float* out_b = (const float*)d_in[6];
    float* out = (float*)d_out;

    float* gP; cudaGetSymbolAddress((void**)&gP, g_P);
    float* gQ; cudaGetSymbolAddress((void**)&gQ, g_Q);
    float* gV; cudaGetSymbolAddress((void**)&gV, g_v);
    float* gXT; cudaGetSymbolAddress((void**)&gXT, g_xt);
    float* gVT; cudaGetSymbolAddress((void**)&gVT, g_vt);
    float* gW1T; cudaGetSymbolAddress((void**)&gW1T, g_w1t);

    embed_kernel<<<dim3(NS / 64, NB), 256>>>(inp, emb);
    w1t_kernel<<<(int)(((size_t)ND * NKT * NI3 * NI) / 256), 256>>>(w1);

    dim3 tb(32, 8);
    for (int d = 0; d < ND; d++) {
        const float* xin = (d % 2 == 0) ? gQ : gP;
        int accm = (d % 2 == 0) ? 1 : 2;

        transpose_kernel<<<dim3(NS / 32, NF / 32, NB), tb>>>(xin, gXT, NF, NF, 0);
        mma_gemm<<<dim3(NS / 128, NI3 / 128, NB), 256>>>(
            w0 + (size_t)d * NI3 * NF, NF, NF, 0, gXT, NF, 0, nullptr, nullptr);
        linattn_kernel<<<dim3(NI, NB), 256>>>();

        transpose_kernel<<<dim3(NS / 32, NI / 32, NB), tb>>>(gV, gVT, NI, NI, 0);
        mma_gemm<<<dim3(NS / 128, NI3 / 128, NB), 256>>>(
            gW1T + (size_t)d * NKT * NI3 * NI, NI, NKT * NI, 1, gVT, NI, 0, nullptr, nullptr);
        linattn_kernel<<<dim3(NI, NB), 256>>>();

        transpose_kernel<<<dim3(NS / 32, NI / 32, NB), tb>>>(gV, gVT, NI, NI, 0);
        mma_gemm<<<dim3(NS / 128, NF / 128, NB), 256>>>(
            w2 + (size_t)d * NF * NI, NI, NI, 0, gVT, NI, accm, nullptr, nullptr);
    }

    // final: concat(P;Q) -> [b][s][512], then out = out_w @ concat + bias
    transpose_kernel<<<dim3(NS / 32, NF / 32, NB), tb>>>(gP, gVT, NF, 2 * NF, 0);
    transpose_kernel<<<dim3(NS / 32, NF / 32, NB), tb>>>(gQ, gVT, NF, 2 * NF, NF);
    mma_gemm<<<dim3(NS / 128, NV / 128, NB), 256>>>(
        out_w, 2 * NF, 2 * NF, 0, gVT, 2 * NF, 3, out, out_b);
}

// round 5
// speedup vs baseline: 4.5549x; 2.2644x over previous
#include <cuda_runtime.h>
#include <cuda_fp16.h>
#include <cstdint>

// Problem dims
#define NB 8
#define NS 4096
#define NF 256
#define NI 512
#define NI3 1536
#define ND 4
#define NKT 7
#define NV 256

#define RSTRIDE 40   // half-elements per smem row (80B) -> conflict-free ldmatrix

// ---------------- device scratch ----------------
__device__ float g_P[(size_t)NB * NF * NS];            // [b][c][s]
__device__ float g_Q[(size_t)NB * NF * NS];            // [b][c][s]
__device__ float g_y[(size_t)NB * NI3 * NS];           // [b][c][s]
__device__ float g_v[(size_t)NB * NI * NS];            // [b][i][s]
__device__ __half g_xth[(size_t)NB * NS * NF];         // [b][s][256] fp16
__device__ __half g_vth[(size_t)NB * NS * NI];         // [b][s][512] fp16 (also concat dst)
__device__ __half g_w1h[(size_t)ND * NKT * NI3 * NI];  // [d][tap][o][i] fp16
__device__ __half g_w0h[(size_t)ND * NI3 * NF];
__device__ __half g_w2h[(size_t)ND * NF * NI];
__device__ __half g_owh[(size_t)NV * 2 * NF];

// ---------------- helpers ----------------
__device__ __forceinline__ uint32_t cvta_s(const void* p) {
    return (uint32_t)__cvta_generic_to_shared(p);
}
__device__ __forceinline__ void cpa16(uint32_t dst, const void* src, int sz) {
    asm volatile("cp.async.cg.shared.global [%0], [%1], 16, %2;"
                 :: "r"(dst), "l"(src), "r"(sz));
}
__device__ __forceinline__ void cp_commit() { asm volatile("cp.async.commit_group;"); }
__device__ __forceinline__ void cp_wait1() { asm volatile("cp.async.wait_group 1;"); }
__device__ __forceinline__ void cp_wait0() { asm volatile("cp.async.wait_group 0;"); }

__device__ __forceinline__ void ldm_x4(uint32_t r[4], uint32_t addr) {
    asm volatile("ldmatrix.sync.aligned.m8n8.x4.shared.b16 {%0,%1,%2,%3}, [%4];"
                 : "=r"(r[0]), "=r"(r[1]), "=r"(r[2]), "=r"(r[3]) : "r"(addr));
}
__device__ __forceinline__ void mma_f16(float c[4], const uint32_t a[4],
                                        uint32_t b0, uint32_t b1) {
    asm volatile(
        "mma.sync.aligned.m16n8k16.row.col.f32.f16.f16.f32 "
        "{%0,%1,%2,%3}, {%4,%5,%6,%7}, {%8,%9}, {%0,%1,%2,%3};"
        : "+f"(c[0]), "+f"(c[1]), "+f"(c[2]), "+f"(c[3])
        : "r"(a[0]), "r"(a[1]), "r"(a[2]), "r"(a[3]), "r"(b0), "r"(b1));
}
__device__ __forceinline__ float mishf(float x) {
    if (x > 20.0f) return x;
    float t = __expf(x);
    float u = t * t + 2.0f * t;
    return x * (u / (u + 2.0f));
}

// ---------------- embedding gather ----------------
__global__ void embed_kernel(const int* __restrict__ inp, const float* __restrict__ emb) {
    int sx = threadIdx.x & 63, cg = threadIdx.x >> 6;
    int s = blockIdx.x * 64 + sx;
    int b = blockIdx.y;
    int idx = inp[b * NS + s];
    const float* er = emb + (size_t)idx * (2 * NF);
#pragma unroll 4
    for (int c = cg; c < NF; c += 4) {
        g_P[((size_t)b * NF + c) * NS + s] = er[c];
        g_Q[((size_t)b * NF + c) * NS + s] = er[c + NF];
    }
}

// ---------------- weight converts ----------------
__global__ void cvt_half_kernel(const float* __restrict__ src, __half* __restrict__ dst,
                                size_t n) {
    size_t i = (size_t)blockIdx.x * 256 + threadIdx.x;
    if (i < n) dst[i] = __float2half(src[i]);
}
// w1 [d][o][i][k] -> [d][k][o][i] fp16
__global__ void w1h_kernel(const float* __restrict__ w1) {
    size_t idx = (size_t)blockIdx.x * 256 + threadIdx.x;
    int i = (int)(idx & (NI - 1));
    size_t r = idx / NI;
    int o = (int)(r % NI3);
    r /= NI3;
    int t = (int)(r % NKT);
    int d = (int)(r / NKT);
    g_w1h[idx] = __float2half(w1[(((size_t)d * NI3 + o) * NI + i) * NKT + t]);
}

// ---------------- activation transpose+convert [b][C][S] f32 -> dst half [b][s][dstride]+doff ----------------
__global__ void transpose_h_kernel(const float* __restrict__ src, __half* __restrict__ dst,
                                   int C, int dstride, int doff) {
    __shared__ float tl[32][33];
    int b = blockIdx.z, c0 = blockIdx.y * 32, s0 = blockIdx.x * 32;
    int tx = threadIdx.x, ty = threadIdx.y;
#pragma unroll
    for (int q = 0; q < 4; q++) {
        int c = ty + q * 8;
        tl[c][tx] = src[((size_t)b * C + c0 + c) * NS + s0 + tx];
    }
    __syncthreads();
#pragma unroll
    for (int q = 0; q < 4; q++) {
        int s = ty + q * 8;
        dst[((size_t)b * NS + s0 + s) * dstride + doff + c0 + tx] = __float2half(tl[tx][s]);
    }
}

// ---------------- lin_attn ----------------
__global__ void linattn_kernel() {
    int i = blockIdx.x, b = blockIdx.y, t = threadIdx.x;
    const float* dr = g_y + ((size_t)b * NI3 + i) * NS + t * 16;
    const float* sc = g_y + ((size_t)b * NI3 + NI + i) * NS + t * 16;
    const float* sh = g_y + ((size_t)b * NI3 + 2 * NI + i) * NS + t * 16;
    float* op = g_v + ((size_t)b * NI + i) * NS + t * 16;

    float loc[16];
#pragma unroll
    for (int q = 0; q < 4; q++) {
        float4 f = ((const float4*)dr)[q];
        loc[q * 4 + 0] = f.x; loc[q * 4 + 1] = f.y;
        loc[q * 4 + 2] = f.z; loc[q * 4 + 3] = f.w;
    }
#pragma unroll
    for (int j = 1; j < 16; j++) loc[j] += loc[j - 1];
    float tot = loc[15];

    float v = tot;
#pragma unroll
    for (int o = 1; o < 32; o <<= 1) {
        float n = __shfl_up_sync(0xffffffffu, v, o);
        if ((t & 31) >= o) v += n;
    }
    __shared__ float wsum[8];
    if ((t & 31) == 31) wsum[t >> 5] = v;
    __syncthreads();
    if (t == 0) {
        float run = 0.0f;
#pragma unroll
        for (int k = 0; k < 8; k++) { float w = wsum[k]; wsum[k] = run; run += w; }
    }
    __syncthreads();
    float excl = wsum[t >> 5] + (v - tot);

    int sbase = t * 16;
#pragma unroll
    for (int q = 0; q < 4; q++) {
        float4 scv = ((const float4*)sc)[q];
        float4 shv = ((const float4*)sh)[q];
        float4 o4;
        o4.x = (excl + loc[q * 4 + 0]) / (float)(sbase + q * 4 + 1) * scv.x + shv.x;
        o4.y = (excl + loc[q * 4 + 1]) / (float)(sbase + q * 4 + 2) * scv.y + shv.y;
        o4.z = (excl + loc[q * 4 + 2]) / (float)(sbase + q * 4 + 3) * scv.z + shv.z;
        o4.w = (excl + loc[q * 4 + 3]) / (float)(sbase + q * 4 + 4) * scv.w + shv.w;
        ((float4*)op)[q] = o4;
    }
}

// ---------------- fp16 warp-MMA GEMM, cp.async double-buffered ----------------
// C[M x Nseq] = A[M x K] * B[K x Nseq] per batch. k-step = 32 per iteration.
// conv: A = g_w1h slice [tap][o][i], B rows tap-shifted with causal zero-fill.
// cmode: 0 -> g_y = mish(acc); 1 -> g_P += acc; 2 -> g_Q += acc; 3 -> Cext = acc + bias.
__global__ void __launch_bounds__(256, 2) hgemm(
    const __half* __restrict__ A, int lda, int conv,
    const __half* __restrict__ B, int bstride, int KT,
    int cmode, float* __restrict__ Cext, const float* __restrict__ bias)
{
    __shared__ __align__(16) __half As[2][128 * RSTRIDE];
    __shared__ __align__(16) __half Bs[2][128 * RSTRIDE];

    int t = threadIdx.x, lane = t & 31, warp = t >> 5;
    int n0 = blockIdx.x * 128, m0 = blockIdx.y * 128, b = blockIdx.z;
    int wm = (warp >> 2) * 64, wn = (warp & 3) * 32;

    float acc[4][4][4];
#pragma unroll
    for (int mi = 0; mi < 4; mi++)
#pragma unroll
        for (int ni = 0; ni < 4; ni++)
#pragma unroll
            for (int q = 0; q < 4; q++) acc[mi][ni][q] = 0.0f;

    int lrow = t >> 1;               // 0..127
    int lch = (t & 1) * 2;           // chunks {0,1} or {2,3}

    uint32_t aS[2] = {cvta_s(As[0]), cvta_s(As[1])};
    uint32_t bS[2] = {cvta_s(Bs[0]), cvta_s(Bs[1])};

    auto issue = [&](int kt) {
        int st = kt & 1;
        uint32_t ad = aS[st] + lrow * (RSTRIDE * 2) + lch * 16;
        uint32_t bd = bS[st] + lrow * (RSTRIDE * 2) + lch * 16;
        const __half *asrc, *bsrc;
        int bsz = 16;
        if (conv) {
            int tap = kt >> 4, ic = (kt & 15) * 32;
            asrc = A + ((size_t)tap * NI3 + m0 + lrow) * NI + ic + lch * 8;
            int s = n0 + lrow + tap - (NKT - 1);
            bsrc = B + ((size_t)b * NS + (s < 0 ? 0 : s)) * bstride + ic + lch * 8;
            bsz = (s < 0) ? 0 : 16;
        } else {
            asrc = A + (size_t)(m0 + lrow) * lda + kt * 32 + lch * 8;
            bsrc = B + ((size_t)b * NS + n0 + lrow) * bstride + kt * 32 + lch * 8;
        }
        cpa16(ad, asrc, 16);
        cpa16(ad + 16, asrc + 8, 16);
        cpa16(bd, bsrc, bsz);
        cpa16(bd + 16, bsrc + 8, bsz);
        cp_commit();
    };

    // ldmatrix lane addressing (both A and B loaded non-transposed:
    // A tile rows are m (k contiguous), B tile rows are n (k contiguous);
    // for m16n8k16, both fragments want lane L -> (row = L/4, k = (L%4)*2).
    int a_row = (lane & 7) + 8 * ((lane >> 3) & 1);   // 0..15
    int a_kb = lane >> 4;                             // 0..1 (16B k-halves)
    int b_coff = (lane & 7) + 8 * (lane >> 4);        // n offset 0..15
    int b_kb = (lane >> 3) & 1;                       // 0..1

    issue(0);
    for (int kt = 0; kt < KT; kt++) {
        if (kt + 1 < KT) {
            issue(kt + 1);
            cp_wait1();
        } else {
            cp_wait0();
        }
        __syncthreads();
        int st = kt & 1;
#pragma unroll
        for (int sub = 0; sub < 2; sub++) {
            uint32_t af[4][4];
#pragma unroll
            for (int mi = 0; mi < 4; mi++) {
                uint32_t addr = aS[st] +
                    (wm + mi * 16 + a_row) * (RSTRIDE * 2) + sub * 32 + a_kb * 16;
                ldm_x4(af[mi], addr);
            }
            uint32_t bf[2][4];
#pragma unroll
            for (int g = 0; g < 2; g++) {
                uint32_t addr = bS[st] +
                    (wn + g * 16 + b_coff) * (RSTRIDE * 2) + sub * 32 + b_kb * 16;
                ldm_x4(bf[g], addr);
            }
#pragma unroll
            for (int mi = 0; mi < 4; mi++)
#pragma unroll
                for (int ni = 0; ni < 4; ni++)
                    mma_f16(acc[mi][ni], af[mi], bf[ni >> 1][(ni & 1) * 2],
                            bf[ni >> 1][(ni & 1) * 2 + 1]);
        }
        __syncthreads();
    }

    // epilogue: rows mlo, mlo+8; cols n, n+1
#pragma unroll
    for (int mi = 0; mi < 4; mi++) {
        int mlo = m0 + wm + mi * 16 + (lane >> 2);
#pragma unroll
        for (int ni = 0; ni < 4; ni++) {
            int n = n0 + wn + ni * 8 + 2 * (lane & 3);
            float* cc = acc[mi][ni];
#pragma unroll
            for (int hh = 0; hh < 2; hh++) {
                int m = mlo + hh * 8;
                float v0 = cc[hh * 2 + 0], v1 = cc[hh * 2 + 1];
                if (cmode == 0) {
                    float2 o = make_float2(mishf(v0), mishf(v1));
                    *(float2*)(g_y + ((size_t)b * NI3 + m) * NS + n) = o;
                } else if (cmode == 1 || cmode == 2) {
                    float* X = (cmode == 1) ? g_P : g_Q;
                    float2* p = (float2*)(X + ((size_t)b * NF + m) * NS + n);
                    float2 e = *p;
                    e.x += v0; e.y += v1;
                    *p = e;
                } else {
                    float bb = bias[m];
                    float2 o = make_float2(v0 + bb, v1 + bb);
                    *(float2*)(Cext + ((size_t)b * NV + m) * NS + n) = o;
                }
            }
        }
    }
}

// ---------------- launch ----------------
extern "C" void kernel_launch(void* const* d_in, const int* in_sizes, int n_in,
                              void* d_out, int out_size) {
    (void)in_sizes; (void)n_in; (void)out_size;
    const int* inp = (const int*)d_in[0];
    const float* emb = (const float*)d_in[1];
    const float* w0 = (const float*)d_in[2];
    const float* w1 = (const float*)d_in[3];
    const float* w2 = (const float*)d_in[4];
    const float* out_w = (const float*)d_in[5];
    const float* out_b = (const float*)d_in[6];
    float* out = (float*)d_out;

    float* gP; cudaGetSymbolAddress((void**)&gP, g_P);
    float* gQ; cudaGetSymbolAddress((void**)&gQ, g_Q);
    float* gV; cudaGetSymbolAddress((void**)&gV, g_v);
    __half* gXTH; cudaGetSymbolAddress((void**)&gXTH, g_xth);
    __half* gVTH; cudaGetSymbolAddress((void**)&gVTH, g_vth);
    __half* gW1H; cudaGetSymbolAddress((void**)&gW1H, g_w1h);
    __half* gW0H; cudaGetSymbolAddress((void**)&gW0H, g_w0h);
    __half* gW2H; cudaGetSymbolAddress((void**)&gW2H, g_w2h);
    __half* gOWH; cudaGetSymbolAddress((void**)&gOWH, g_owh);

    embed_kernel<<<dim3(NS / 64, NB), 256>>>(inp, emb);
    w1h_kernel<<<(int)(((size_t)ND * NKT * NI3 * NI) / 256), 256>>>(w1);
    {
        size_t n0c = (size_t)ND * NI3 * NF;
        cvt_half_kernel<<<(int)((n0c + 255) / 256), 256>>>(w0, gW0H, n0c);
        size_t n2c = (size_t)ND * NF * NI;
        cvt_half_kernel<<<(int)((n2c + 255) / 256), 256>>>(w2, gW2H, n2c);
        size_t noc = (size_t)NV * 2 * NF;
        cvt_half_kernel<<<(int)((noc + 255) / 256), 256>>>(out_w, gOWH, noc);
    }

    dim3 tb(32, 8);
    for (int d = 0; d < ND; d++) {
        const float* xin = (d % 2 == 0) ? gQ : gP;
        int accm = (d % 2 == 0) ? 1 : 2;

        transpose_h_kernel<<<dim3(NS / 32, NF / 32, NB), tb>>>(xin, gXTH, NF, NF, 0);
        hgemm<<<dim3(NS / 128, NI3 / 128, NB), 256>>>(
            gW0H + (size_t)d * NI3 * NF, NF, 0, gXTH, NF, NF / 32, 0, nullptr, nullptr);
        linattn_kernel<<<dim3(NI, NB), 256>>>();

        transpose_h_kernel<<<dim3(NS / 32, NI / 32, NB), tb>>>(gV, gVTH, NI, NI, 0);
        hgemm<<<dim3(NS / 128, NI3 / 128, NB), 256>>>(
            gW1H + (size_t)d * NKT * NI3 * NI, NI, 1, gVTH, NI, NKT * NI / 32,
            0, nullptr, nullptr);
        linattn_kernel<<<dim3(NI, NB), 256>>>();

        transpose_h_kernel<<<dim3(NS / 32, NI / 32, NB), tb>>>(gV, gVTH, NI, NI, 0);
        hgemm<<<dim3(NS / 128, NF / 128, NB), 256>>>(
            gW2H + (size_t)d * NF * NI, NI, 0, gVTH, NI, NI / 32, accm, nullptr, nullptr);
    }

    // final: concat(P;Q) -> [b][s][512] half, then out = out_w @ concat + bias
    transpose_h_kernel<<<dim3(NS / 32, NF / 32, NB), tb>>>(gP, gVTH, NF, 2 * NF, 0);
    transpose_h_kernel<<<dim3(NS / 32, NF / 32, NB), tb>>>(gQ, gVTH, NF, 2 * NF, NF);
    hgemm<<<dim3(NS / 128, NV / 128, NB), 256>>>(
        gOWH, 2 * NF, 0, gVTH, 2 * NF, 2 * NF / 32, 3, out, out_b);
}